// round 5
// baseline (speedup 1.0000x reference)
#include <cuda_runtime.h>
#include <math.h>

#define BB 2
#define CC 128
#define TT 512
#define FF 64
#define HH 32
#define DD 32

typedef unsigned long long u64;

// -------- f32x2 packed-FMA helpers (sm_103a) --------
__device__ __forceinline__ u64 pack2(float lo, float hi) {
    u64 r; asm("mov.b64 %0,{%1,%2};" : "=l"(r) : "f"(lo), "f"(hi)); return r;
}
__device__ __forceinline__ void unpack2(u64 v, float& a, float& b) {
    asm("mov.b64 {%0,%1},%2;" : "=f"(a), "=f"(b) : "l"(v));
}
__device__ __forceinline__ u64 fma2(u64 a, u64 b, u64 c) {
    u64 d; asm("fma.rn.f32x2 %0,%1,%2,%3;" : "=l"(d) : "l"(a), "l"(b), "l"(c)); return d;
}

// -------- scratch (device globals: allocation-free) --------
__device__ float g_xm1[BB*HH*TT*FF];   // (b,h,t,f)
__device__ float g_xf1[BB*HH*TT*FF];   // (b,h,t,f)
__device__ float g_corr[BB*HH*TT*DD];  // (b,h,t,d)
__device__ float g_w[BB*TT*DD];        // (b,t,d) softmax weights

// ============================================================
// K1 (fused both projections): out[b,h,t,f] = sum_c x[b,c,t,f]*w[c,h] + bias[h]
// thread = (b, t-pair, f); 2 t-rows per thread. Weights via broadcast
// LDS.128. Double-buffered LDG prefetch across c0 blocks.
// ============================================================
__global__ void __launch_bounds__(256) proj_kernel(
    const float* __restrict__ xm, const float* __restrict__ xf,
    const float* __restrict__ w1, const float* __restrict__ b1,
    const float* __restrict__ w2, const float* __restrict__ b2)
{
    __shared__ __align__(16) float ws[CC*HH];   // [c][h]
    __shared__ float bs[HH];
    int which = blockIdx.y;
    const float* x    = which ? xf : xm;
    const float* w    = which ? w2 : w1;
    const float* bias = which ? b2 : b1;
    float* outg = which ? g_xf1 : g_xm1;

    int tid = threadIdx.x;
    for (int i = tid; i < CC*HH; i += 256) ws[i] = w[i];
    if (tid < HH) bs[tid] = bias[tid];
    __syncthreads();

    int f  = tid & 63;
    int tp = tid >> 6;                       // 0..3
    int bx = blockIdx.x;
    int b  = bx >> 6;
    int t  = (((bx & 63) << 2) + tp) << 1;   // even t; thread does t and t+1

    u64 acc0[16], acc1[16];
#pragma unroll
    for (int i = 0; i < 16; i++) { acc0[i] = 0ull; acc1[i] = 0ull; }

    const float* xp = x + ((size_t)b*CC*TT + t)*FF + f;

    float va[8], vb[8];
#pragma unroll
    for (int j = 0; j < 8; j++) {
        const float* p = xp + (size_t)j*TT*FF;
        va[j] = p[0];
        vb[j] = p[FF];
    }

#pragma unroll 1
    for (int c0 = 0; c0 < CC; c0 += 8) {
        float na[8], nb[8];
        if (c0 + 8 < CC) {
#pragma unroll
            for (int j = 0; j < 8; j++) {
                const float* p = xp + (size_t)(c0+8+j)*TT*FF;
                na[j] = p[0];
                nb[j] = p[FF];
            }
        }
#pragma unroll
        for (int j = 0; j < 8; j++) {
            u64 pa = pack2(va[j], va[j]);
            u64 pb = pack2(vb[j], vb[j]);
            const ulonglong2* wq = (const ulonglong2*)(ws + (c0+j)*HH);
#pragma unroll
            for (int q = 0; q < 8; q++) {
                ulonglong2 wv = wq[q];
                acc0[2*q]   = fma2(pa, wv.x, acc0[2*q]);
                acc0[2*q+1] = fma2(pa, wv.y, acc0[2*q+1]);
                acc1[2*q]   = fma2(pb, wv.x, acc1[2*q]);
                acc1[2*q+1] = fma2(pb, wv.y, acc1[2*q+1]);
            }
        }
#pragma unroll
        for (int j = 0; j < 8; j++) { va[j] = na[j]; vb[j] = nb[j]; }
    }

#pragma unroll
    for (int q = 0; q < 16; q++) {
        float a0, a1, c0v, c1v;
        unpack2(acc0[q], a0, a1);
        unpack2(acc1[q], c0v, c1v);
        int h0 = 2*q, h1 = 2*q+1;
        float* o0 = outg + ((size_t)(b*HH+h0)*TT + t)*FF + f;
        float* o1 = outg + ((size_t)(b*HH+h1)*TT + t)*FF + f;
        o0[0]  = a0  + bs[h0];
        o0[FF] = c0v + bs[h0];
        o1[0]  = a1  + bs[h1];
        o1[FF] = c1v + bs[h1];
    }
}

// ============================================================
// K2: banded correlation (register-tiled band-GEMM)
// corr[b,h,t,d] = sum_f xm1[b,h,t,f] * xf1[b,h,t+d-31,f]   (0-padded)
// ============================================================
#define K2T 64
#define K2S 70
__global__ void __launch_bounds__(256) corr_kernel()
{
    __shared__ float sm[K2T*K2S];
    __shared__ float sf[(K2T+31)*K2S];

    int b = blockIdx.z, h = blockIdx.y, t0 = blockIdx.x * K2T;
    int tid = threadIdx.x;   // 256

    const float* xmp = g_xm1 + ((size_t)(b*HH+h)*TT)*FF;
    const float* xfp = g_xf1 + ((size_t)(b*HH+h)*TT)*FF;

    for (int i = tid; i < K2T*FF; i += 256) {
        int r = i >> 6, fc = i & 63;
        sm[r*K2S + fc] = xmp[(size_t)(t0+r)*FF + fc];
    }
    for (int i = tid; i < (K2T+31)*FF; i += 256) {
        int r = i >> 6, fc = i & 63;
        int tt = t0 + r - 31;
        sf[r*K2S + fc] = (tt >= 0) ? xfp[(size_t)tt*FF + fc] : 0.f;
    }
    __syncthreads();

    int tl0 = (tid >> 3) << 1;   // 0,2,...,62
    int d0  = (tid & 7)  << 2;   // 0,4,...,28

    u64 acc[2][4];
#pragma unroll
    for (int i = 0; i < 2; i++)
#pragma unroll
        for (int j = 0; j < 4; j++) acc[i][j] = 0ull;

#pragma unroll 4
    for (int fcp = 0; fcp < FF/2; fcp++) {
        u64 a[2], br[5];
#pragma unroll
        for (int i = 0; i < 2; i++)
            a[i] = *(const u64*)(sm + (tl0+i)*K2S + fcp*2);
#pragma unroll
        for (int k = 0; k < 5; k++)
            br[k] = *(const u64*)(sf + (tl0+d0+k)*K2S + fcp*2);
#pragma unroll
        for (int i = 0; i < 2; i++)
#pragma unroll
            for (int j = 0; j < 4; j++)
                acc[i][j] = fma2(a[i], br[i+j], acc[i][j]);
    }

#pragma unroll
    for (int i = 0; i < 2; i++) {
        float4 v; float x0, x1;
        unpack2(acc[i][0], x0, x1); v.x = x0 + x1;
        unpack2(acc[i][1], x0, x1); v.y = x0 + x1;
        unpack2(acc[i][2], x0, x1); v.z = x0 + x1;
        unpack2(acc[i][3], x0, x1); v.w = x0 + x1;
        *(float4*)(g_corr + (((size_t)(b*HH+h)*TT + (t0+tl0+i))*DD + d0)) = v;
    }
}

// ============================================================
// K3: 5x3 conv over (t,d) reduced over h, + bias, mask, softmax over d
// block = (b, 8-t tile) -> grid 128. Stage 16 heads at once (2 phases).
// ============================================================
__global__ void conv_softmax_kernel(const float* __restrict__ wc,
                                    const float* __restrict__ bc)
{
    __shared__ float sc[16][12*36];
    __shared__ float wcs[HH*15];
    int tid = threadIdx.x;  // 256
    int b = blockIdx.y, t0 = blockIdx.x * 8;

    for (int i = tid; i < HH*15; i += 256) wcs[i] = wc[i];

    int d  = tid & 31;
    int tl = tid >> 5;
    float acc = 0.f;

#pragma unroll 1
    for (int ph = 0; ph < 2; ph++) {
        __syncthreads();
        const float* cpb = g_corr + ((size_t)(b*HH + ph*16)*TT)*DD;
        for (int i = tid; i < 16*12*34; i += 256) {
            int h   = i / 408;
            int rem = i - h*408;
            int r   = rem / 34;
            int col = rem - r*34;
            int tt = t0 - 3 + r, dd = col - 1;
            float v = 0.f;
            if (tt >= 0 && tt < TT && dd >= 0 && dd < DD)
                v = cpb[(size_t)h*TT*DD + (size_t)tt*DD + dd];
            sc[h][r*36 + col] = v;
        }
        __syncthreads();
#pragma unroll 1
        for (int h = 0; h < 16; h++) {
            const float* s  = sc[h] + tl*36 + d;
            const float* wv = wcs + (ph*16 + h)*15;
#pragma unroll
            for (int kh = 0; kh < 5; kh++)
#pragma unroll
                for (int kw = 0; kw < 3; kw++)
                    acc = fmaf(s[kh*36 + kw], wv[kh*3 + kw], acc);
        }
    }

    acc += bc[0];
    int t = t0 + tl;
    if (t + d < DD - 1) acc = -1e13f;

    float m = acc;
#pragma unroll
    for (int o = 16; o; o >>= 1) m = fmaxf(m, __shfl_xor_sync(0xffffffffu, m, o));
    float e = expf(acc - m);
    float s = e;
#pragma unroll
    for (int o = 16; o; o >>= 1) s += __shfl_xor_sync(0xffffffffu, s, o);

    g_w[((size_t)b*TT + t)*DD + d] = e / s;
}

// ============================================================
// K4: out[b,c,t,f] = sum_d w[b,t,d] * xf[b,c,t+d-31,f]
// 128 threads: thread = (f-half 0..7 -> 8 floats, t-group 0..15 -> 4 t).
// Per iter: 2 LDS.128 + 4 broadcast LDS.64 + 16 FFMA2 -> fma-bound.
// Weights duplicated (w,w) zero-padded over d in [-3,34]: no predicates.
// ============================================================
#define K4T 64
#define K4W 38   // padded weight width: d in [-3, 34]
__global__ void __launch_bounds__(128) out_kernel(const float* __restrict__ xf,
                                                  float* __restrict__ out)
{
    __shared__ __align__(16) float sx[(K4T+31)*FF];  // 24320 B
    __shared__ u64 swd[K4T*K4W];                     // 19456 B

    int b = blockIdx.z, c = blockIdx.y, t0 = blockIdx.x * K4T;
    int tid = threadIdx.x;  // 128

    const float* xp = xf + ((size_t)(b*CC + c)*TT)*FF;
    for (int i = tid; i < (K4T+31)*FF; i += 128) {
        int r = i >> 6;
        int tt = t0 + r - 31;
        sx[i] = (tt >= 0) ? xp[(size_t)tt*FF + (i & 63)] : 0.f;
    }
    const float* wp = g_w + ((size_t)b*TT + t0)*DD;
    for (int i = tid; i < K4T*K4W; i += 128) {
        int tl = i / K4W, j = i - tl*K4W;
        int dd = j - 3;
        float v = (dd >= 0 && dd < DD) ? wp[tl*DD + dd] : 0.f;
        swd[i] = pack2(v, v);
    }
    __syncthreads();

    int fh = tid & 7;            // f = 8*fh .. 8*fh+7
    int tb = (tid >> 3) << 2;    // t_local base: 0,4,...,60

    u64 acc[4][4];
#pragma unroll
    for (int i = 0; i < 4; i++)
#pragma unroll
        for (int k = 0; k < 4; k++) acc[i][k] = 0ull;

    const float* xrow = sx + tb*FF + fh*8;
    const u64* w0 = swd + (tb+0)*K4W + 3;
    const u64* w1 = swd + (tb+1)*K4W + 2;
    const u64* w2 = swd + (tb+2)*K4W + 1;
    const u64* w3 = swd + (tb+3)*K4W + 0;

#pragma unroll 5
    for (int rl = 0; rl < 35; rl++) {
        ulonglong2 xa = *(const ulonglong2*)(xrow + rl*FF);
        ulonglong2 xb = *(const ulonglong2*)(xrow + rl*FF + 4);
        u64 a0 = w0[rl], a1 = w1[rl], a2 = w2[rl], a3 = w3[rl];
        acc[0][0] = fma2(xa.x, a0, acc[0][0]);
        acc[0][1] = fma2(xa.y, a0, acc[0][1]);
        acc[0][2] = fma2(xb.x, a0, acc[0][2]);
        acc[0][3] = fma2(xb.y, a0, acc[0][3]);
        acc[1][0] = fma2(xa.x, a1, acc[1][0]);
        acc[1][1] = fma2(xa.y, a1, acc[1][1]);
        acc[1][2] = fma2(xb.x, a1, acc[1][2]);
        acc[1][3] = fma2(xb.y, a1, acc[1][3]);
        acc[2][0] = fma2(xa.x, a2, acc[2][0]);
        acc[2][1] = fma2(xa.y, a2, acc[2][1]);
        acc[2][2] = fma2(xb.x, a2, acc[2][2]);
        acc[2][3] = fma2(xb.y, a2, acc[2][3]);
        acc[3][0] = fma2(xa.x, a3, acc[3][0]);
        acc[3][1] = fma2(xa.y, a3, acc[3][1]);
        acc[3][2] = fma2(xb.x, a3, acc[3][2]);
        acc[3][3] = fma2(xb.y, a3, acc[3][3]);
    }

    float* op = out + ((size_t)(b*CC + c)*TT + (t0 + tb))*FF + fh*8;
#pragma unroll
    for (int i = 0; i < 4; i++) {
        float4 v0, v1;
        unpack2(acc[i][0], v0.x, v0.y);
        unpack2(acc[i][1], v0.z, v0.w);
        unpack2(acc[i][2], v1.x, v1.y);
        unpack2(acc[i][3], v1.z, v1.w);
        *(float4*)(op + (size_t)i*FF)     = v0;
        *(float4*)(op + (size_t)i*FF + 4) = v1;
    }
}

// ============================================================
extern "C" void kernel_launch(void* const* d_in, const int* in_sizes, int n_in,
                              void* d_out, int out_size)
{
    const float* xm = (const float*)d_in[0];
    const float* xf = (const float*)d_in[1];
    const float* w1 = (const float*)d_in[2];
    const float* b1 = (const float*)d_in[3];
    const float* w2 = (const float*)d_in[4];
    const float* b2 = (const float*)d_in[5];
    const float* wc = (const float*)d_in[6];
    const float* bc = (const float*)d_in[7];
    float* out = (float*)d_out;

    (void)in_sizes; (void)n_in; (void)out_size;

    proj_kernel<<<dim3(128, 2), 256>>>(xm, xf, w1, b1, w2, b2);

    dim3 g2(TT/K2T, HH, BB);
    corr_kernel<<<g2, 256>>>();

    dim3 g3(TT/8, BB);
    conv_softmax_kernel<<<g3, 256>>>(wc, bc);

    dim3 g4(TT/K4T, CC, BB);
    out_kernel<<<g4, 128>>>(xf, out);
}

// round 6
// speedup vs baseline: 1.2613x; 1.2613x over previous
#include <cuda_runtime.h>
#include <math.h>

#define BB 2
#define CC 128
#define TT 512
#define FF 64
#define HH 32
#define DD 32

typedef unsigned long long u64;

// -------- f32x2 packed-FMA helpers (sm_103a) --------
__device__ __forceinline__ u64 pack2(float lo, float hi) {
    u64 r; asm("mov.b64 %0,{%1,%2};" : "=l"(r) : "f"(lo), "f"(hi)); return r;
}
__device__ __forceinline__ void unpack2(u64 v, float& a, float& b) {
    asm("mov.b64 {%0,%1},%2;" : "=f"(a), "=f"(b) : "l"(v));
}
__device__ __forceinline__ u64 fma2(u64 a, u64 b, u64 c) {
    u64 d; asm("fma.rn.f32x2 %0,%1,%2,%3;" : "=l"(d) : "l"(a), "l"(b), "l"(c)); return d;
}

// -------- scratch (device globals: allocation-free) --------
__device__ float g_xm1[BB*HH*TT*FF];   // (b,h,t,f)
__device__ float g_xf1[BB*HH*TT*FF];   // (b,h,t,f)
__device__ float g_corr[BB*HH*TT*DD];  // (b,h,t,d)
__device__ float g_w[BB*TT*DD];        // (b,t,d) softmax weights

// ============================================================
// K1 (fused both projections): out[b,h,t,f] = sum_c x[b,c,t,f]*w[c,h] + bias[h]
// 128-thread blocks, 512 blocks total (finer wave granularity, higher occ).
// thread = (b, t-pair, f); 2 t-rows per thread. Weights via warp-uniform
// broadcast LDS.128 (1 wavefront each).
// ============================================================
__global__ void __launch_bounds__(128) proj_kernel(
    const float* __restrict__ xm, const float* __restrict__ xf,
    const float* __restrict__ w1, const float* __restrict__ b1,
    const float* __restrict__ w2, const float* __restrict__ b2)
{
    __shared__ __align__(16) float ws[CC*HH];   // [c][h]
    __shared__ float bs[HH];
    int which = blockIdx.y;
    const float* x    = which ? xf : xm;
    const float* w    = which ? w2 : w1;
    const float* bias = which ? b2 : b1;
    float* outg = which ? g_xf1 : g_xm1;

    int tid = threadIdx.x;   // 128
    for (int i = tid; i < CC*HH; i += 128) ws[i] = w[i];
    if (tid < HH) bs[tid] = bias[tid];
    __syncthreads();

    int f  = tid & 63;
    int tp = tid >> 6;                  // 0..1
    int bx = blockIdx.x;                // 0..255
    int b  = bx >> 7;
    int pos = bx & 127;                 // 4 t per block
    int t  = (pos*2 + tp) << 1;         // even t; thread does t and t+1

    u64 acc0[16], acc1[16];
#pragma unroll
    for (int i = 0; i < 16; i++) { acc0[i] = 0ull; acc1[i] = 0ull; }

    const float* xp = x + ((size_t)b*CC*TT + t)*FF + f;

#pragma unroll 1
    for (int c0 = 0; c0 < CC; c0 += 8) {
        float va[8], vb[8];
#pragma unroll
        for (int j = 0; j < 8; j++) {
            const float* p = xp + (size_t)(c0+j)*TT*FF;
            va[j] = p[0];
            vb[j] = p[FF];
        }
#pragma unroll
        for (int j = 0; j < 8; j++) {
            u64 pa = pack2(va[j], va[j]);
            u64 pb = pack2(vb[j], vb[j]);
            const ulonglong2* wq = (const ulonglong2*)(ws + (c0+j)*HH);
#pragma unroll
            for (int q = 0; q < 8; q++) {
                ulonglong2 wv = wq[q];
                acc0[2*q]   = fma2(pa, wv.x, acc0[2*q]);
                acc0[2*q+1] = fma2(pa, wv.y, acc0[2*q+1]);
                acc1[2*q]   = fma2(pb, wv.x, acc1[2*q]);
                acc1[2*q+1] = fma2(pb, wv.y, acc1[2*q+1]);
            }
        }
    }

#pragma unroll
    for (int q = 0; q < 16; q++) {
        float a0, a1, c0v, c1v;
        unpack2(acc0[q], a0, a1);
        unpack2(acc1[q], c0v, c1v);
        int h0 = 2*q, h1 = 2*q+1;
        float* o0 = outg + ((size_t)(b*HH+h0)*TT + t)*FF + f;
        float* o1 = outg + ((size_t)(b*HH+h1)*TT + t)*FF + f;
        o0[0]  = a0  + bs[h0];
        o0[FF] = c0v + bs[h0];
        o1[0]  = a1  + bs[h1];
        o1[FF] = c1v + bs[h1];
    }
}

// ============================================================
// K2: banded correlation (register-tiled band-GEMM)
// corr[b,h,t,d] = sum_f xm1[b,h,t,f] * xf1[b,h,t+d-31,f]   (0-padded)
// ============================================================
#define K2T 64
#define K2S 70
__global__ void __launch_bounds__(256) corr_kernel()
{
    __shared__ float sm[K2T*K2S];
    __shared__ float sf[(K2T+31)*K2S];

    int b = blockIdx.z, h = blockIdx.y, t0 = blockIdx.x * K2T;
    int tid = threadIdx.x;   // 256

    const float* xmp = g_xm1 + ((size_t)(b*HH+h)*TT)*FF;
    const float* xfp = g_xf1 + ((size_t)(b*HH+h)*TT)*FF;

    for (int i = tid; i < K2T*FF; i += 256) {
        int r = i >> 6, fc = i & 63;
        sm[r*K2S + fc] = xmp[(size_t)(t0+r)*FF + fc];
    }
    for (int i = tid; i < (K2T+31)*FF; i += 256) {
        int r = i >> 6, fc = i & 63;
        int tt = t0 + r - 31;
        sf[r*K2S + fc] = (tt >= 0) ? xfp[(size_t)tt*FF + fc] : 0.f;
    }
    __syncthreads();

    int tl0 = (tid >> 3) << 1;   // 0,2,...,62
    int d0  = (tid & 7)  << 2;   // 0,4,...,28

    u64 acc[2][4];
#pragma unroll
    for (int i = 0; i < 2; i++)
#pragma unroll
        for (int j = 0; j < 4; j++) acc[i][j] = 0ull;

#pragma unroll 4
    for (int fcp = 0; fcp < FF/2; fcp++) {
        u64 a[2], br[5];
#pragma unroll
        for (int i = 0; i < 2; i++)
            a[i] = *(const u64*)(sm + (tl0+i)*K2S + fcp*2);
#pragma unroll
        for (int k = 0; k < 5; k++)
            br[k] = *(const u64*)(sf + (tl0+d0+k)*K2S + fcp*2);
#pragma unroll
        for (int i = 0; i < 2; i++)
#pragma unroll
            for (int j = 0; j < 4; j++)
                acc[i][j] = fma2(a[i], br[i+j], acc[i][j]);
    }

#pragma unroll
    for (int i = 0; i < 2; i++) {
        float4 v; float x0, x1;
        unpack2(acc[i][0], x0, x1); v.x = x0 + x1;
        unpack2(acc[i][1], x0, x1); v.y = x0 + x1;
        unpack2(acc[i][2], x0, x1); v.z = x0 + x1;
        unpack2(acc[i][3], x0, x1); v.w = x0 + x1;
        *(float4*)(g_corr + (((size_t)(b*HH+h)*TT + (t0+tl0+i))*DD + d0)) = v;
    }
}

// ============================================================
// K3: 5x3 conv over (t,d) reduced over h, + bias, mask, softmax over d
// block = (b, 8-t tile) -> grid 128. Stage 16 heads at once (2 phases).
// ============================================================
__global__ void conv_softmax_kernel(const float* __restrict__ wc,
                                    const float* __restrict__ bc)
{
    __shared__ float sc[16][12*36];
    __shared__ float wcs[HH*15];
    int tid = threadIdx.x;  // 256
    int b = blockIdx.y, t0 = blockIdx.x * 8;

    for (int i = tid; i < HH*15; i += 256) wcs[i] = wc[i];

    int d  = tid & 31;
    int tl = tid >> 5;
    float acc = 0.f;

#pragma unroll 1
    for (int ph = 0; ph < 2; ph++) {
        __syncthreads();
        const float* cpb = g_corr + ((size_t)(b*HH + ph*16)*TT)*DD;
        for (int i = tid; i < 16*12*34; i += 256) {
            int h   = i / 408;
            int rem = i - h*408;
            int r   = rem / 34;
            int col = rem - r*34;
            int tt = t0 - 3 + r, dd = col - 1;
            float v = 0.f;
            if (tt >= 0 && tt < TT && dd >= 0 && dd < DD)
                v = cpb[(size_t)h*TT*DD + (size_t)tt*DD + dd];
            sc[h][r*36 + col] = v;
        }
        __syncthreads();
#pragma unroll 1
        for (int h = 0; h < 16; h++) {
            const float* s  = sc[h] + tl*36 + d;
            const float* wv = wcs + (ph*16 + h)*15;
#pragma unroll
            for (int kh = 0; kh < 5; kh++)
#pragma unroll
                for (int kw = 0; kw < 3; kw++)
                    acc = fmaf(s[kh*36 + kw], wv[kh*3 + kw], acc);
        }
    }

    acc += bc[0];
    int t = t0 + tl;
    if (t + d < DD - 1) acc = -1e13f;

    float m = acc;
#pragma unroll
    for (int o = 16; o; o >>= 1) m = fmaxf(m, __shfl_xor_sync(0xffffffffu, m, o));
    float e = expf(acc - m);
    float s = e;
#pragma unroll
    for (int o = 16; o; o >>= 1) s += __shfl_xor_sync(0xffffffffu, s, o);

    g_w[((size_t)b*TT + t)*DD + d] = e / s;
}

// ============================================================
// K4: out[b,c,t,f] = sum_d w[b,t,d] * xf[b,c,t+d-31,f]
// (R4 config: 256 threads, thread = (f-quad 0..15, t-group 0..15 of 4 t).)
// Weights duplicated (w,w) zero-padded over d in [-3,34]:
// inner loop has ZERO predicates/bounds -> pure LDS+FFMA2.
// ============================================================
#define K4T 64
#define K4W 38   // padded weight width: d in [-3, 34]
__global__ void __launch_bounds__(256) out_kernel(const float* __restrict__ xf,
                                                  float* __restrict__ out)
{
    __shared__ __align__(16) float sx[(K4T+31)*FF];  // 24320 B
    __shared__ u64 swd[K4T*K4W];                     // 19456 B

    int b = blockIdx.z, c = blockIdx.y, t0 = blockIdx.x * K4T;
    int tid = threadIdx.x;  // 256

    const float* xp = xf + ((size_t)(b*CC + c)*TT)*FF;
    for (int i = tid; i < (K4T+31)*FF; i += 256) {
        int r = i >> 6;
        int tt = t0 + r - 31;
        sx[i] = (tt >= 0) ? xp[(size_t)tt*FF + (i & 63)] : 0.f;
    }
    const float* wp = g_w + ((size_t)b*TT + t0)*DD;
    for (int i = tid; i < K4T*K4W; i += 256) {
        int tl = i / K4W, j = i - tl*K4W;
        int dd = j - 3;
        float v = (dd >= 0 && dd < DD) ? wp[tl*DD + dd] : 0.f;
        swd[i] = pack2(v, v);
    }
    __syncthreads();

    int fq = tid & 15;            // f = 4*fq .. 4*fq+3
    int tb = (tid >> 4) << 2;     // t_local base: 0,4,...,60

    u64 acc[4][2];
#pragma unroll
    for (int i = 0; i < 4; i++) { acc[i][0] = 0ull; acc[i][1] = 0ull; }

    const float* xrow = sx + tb*FF + fq*4;
    const u64* w0 = swd + (tb+0)*K4W + 3;
    const u64* w1 = swd + (tb+1)*K4W + 2;
    const u64* w2 = swd + (tb+2)*K4W + 1;
    const u64* w3 = swd + (tb+3)*K4W + 0;

#pragma unroll 5
    for (int rl = 0; rl < 35; rl++) {
        ulonglong2 xv = *(const ulonglong2*)(xrow + rl*FF);
        u64 a0 = w0[rl], a1 = w1[rl], a2 = w2[rl], a3 = w3[rl];
        acc[0][0] = fma2(xv.x, a0, acc[0][0]);
        acc[0][1] = fma2(xv.y, a0, acc[0][1]);
        acc[1][0] = fma2(xv.x, a1, acc[1][0]);
        acc[1][1] = fma2(xv.y, a1, acc[1][1]);
        acc[2][0] = fma2(xv.x, a2, acc[2][0]);
        acc[2][1] = fma2(xv.y, a2, acc[2][1]);
        acc[3][0] = fma2(xv.x, a3, acc[3][0]);
        acc[3][1] = fma2(xv.y, a3, acc[3][1]);
    }

    float* op = out + ((size_t)(b*CC + c)*TT + (t0 + tb))*FF + fq*4;
#pragma unroll
    for (int i = 0; i < 4; i++) {
        float4 v;
        unpack2(acc[i][0], v.x, v.y);
        unpack2(acc[i][1], v.z, v.w);
        *(float4*)(op + (size_t)i*FF) = v;
    }
}

// ============================================================
extern "C" void kernel_launch(void* const* d_in, const int* in_sizes, int n_in,
                              void* d_out, int out_size)
{
    const float* xm = (const float*)d_in[0];
    const float* xf = (const float*)d_in[1];
    const float* w1 = (const float*)d_in[2];
    const float* b1 = (const float*)d_in[3];
    const float* w2 = (const float*)d_in[4];
    const float* b2 = (const float*)d_in[5];
    const float* wc = (const float*)d_in[6];
    const float* bc = (const float*)d_in[7];
    float* out = (float*)d_out;

    (void)in_sizes; (void)n_in; (void)out_size;

    proj_kernel<<<dim3(256, 2), 128>>>(xm, xf, w1, b1, w2, b2);

    dim3 g2(TT/K2T, HH, BB);
    corr_kernel<<<g2, 256>>>();

    dim3 g3(TT/8, BB);
    conv_softmax_kernel<<<g3, 256>>>(wc, bc);

    dim3 g4(TT/K4T, CC, BB);
    out_kernel<<<g4, 256>>>(xf, out);
}

// round 7
// speedup vs baseline: 1.2984x; 1.0295x over previous
#include <cuda_runtime.h>
#include <math.h>

#define BB 2
#define CC 128
#define TT 512
#define FF 64
#define HH 32
#define DD 32

typedef unsigned long long u64;

// -------- f32x2 packed-FMA helpers (sm_103a) --------
__device__ __forceinline__ u64 pack2(float lo, float hi) {
    u64 r; asm("mov.b64 %0,{%1,%2};" : "=l"(r) : "f"(lo), "f"(hi)); return r;
}
__device__ __forceinline__ void unpack2(u64 v, float& a, float& b) {
    asm("mov.b64 {%0,%1},%2;" : "=f"(a), "=f"(b) : "l"(v));
}
__device__ __forceinline__ u64 fma2(u64 a, u64 b, u64 c) {
    u64 d; asm("fma.rn.f32x2 %0,%1,%2,%3;" : "=l"(d) : "l"(a), "l"(b), "l"(c)); return d;
}

// -------- scratch (device globals: allocation-free) --------
__device__ float g_xm1[BB*HH*TT*FF];   // (b,h,t,f)
__device__ float g_xf1[BB*HH*TT*FF];   // (b,h,t,f)
__device__ float g_corr[BB*HH*TT*DD];  // (b,h,t,d)
__device__ float g_w[BB*TT*DD];        // (b,t,d) softmax weights

// ============================================================
// K1 (fused both projections): out[b,h,t,f] = sum_c x[b,c,t,f]*w[c,h] + bias[h]
// (exact R4 config: 256 threads, dim3(128,2))
// thread = (b, t-pair, f); 2 t-rows per thread. Weights via warp-uniform
// broadcast LDS.128.
// ============================================================
__global__ void __launch_bounds__(256) proj_kernel(
    const float* __restrict__ xm, const float* __restrict__ xf,
    const float* __restrict__ w1, const float* __restrict__ b1,
    const float* __restrict__ w2, const float* __restrict__ b2)
{
    __shared__ __align__(16) float ws[CC*HH];   // [c][h]
    __shared__ float bs[HH];
    int which = blockIdx.y;
    const float* x    = which ? xf : xm;
    const float* w    = which ? w2 : w1;
    const float* bias = which ? b2 : b1;
    float* outg = which ? g_xf1 : g_xm1;

    int tid = threadIdx.x;
    for (int i = tid; i < CC*HH; i += 256) ws[i] = w[i];
    if (tid < HH) bs[tid] = bias[tid];
    __syncthreads();

    int f  = tid & 63;
    int tp = tid >> 6;                       // 0..3
    int bx = blockIdx.x;
    int b  = bx >> 6;
    int t  = (((bx & 63) << 2) + tp) << 1;   // even t; thread does t and t+1

    u64 acc0[16], acc1[16];
#pragma unroll
    for (int i = 0; i < 16; i++) { acc0[i] = 0ull; acc1[i] = 0ull; }

    const float* xp = x + ((size_t)b*CC*TT + t)*FF + f;

#pragma unroll 1
    for (int c0 = 0; c0 < CC; c0 += 8) {
        float va[8], vb[8];
#pragma unroll
        for (int j = 0; j < 8; j++) {
            const float* p = xp + (size_t)(c0+j)*TT*FF;
            va[j] = p[0];
            vb[j] = p[FF];
        }
#pragma unroll
        for (int j = 0; j < 8; j++) {
            u64 pa = pack2(va[j], va[j]);
            u64 pb = pack2(vb[j], vb[j]);
            const ulonglong2* wq = (const ulonglong2*)(ws + (c0+j)*HH);
#pragma unroll
            for (int q = 0; q < 8; q++) {
                ulonglong2 wv = wq[q];
                acc0[2*q]   = fma2(pa, wv.x, acc0[2*q]);
                acc0[2*q+1] = fma2(pa, wv.y, acc0[2*q+1]);
                acc1[2*q]   = fma2(pb, wv.x, acc1[2*q]);
                acc1[2*q+1] = fma2(pb, wv.y, acc1[2*q+1]);
            }
        }
    }

#pragma unroll
    for (int q = 0; q < 16; q++) {
        float a0, a1, c0v, c1v;
        unpack2(acc0[q], a0, a1);
        unpack2(acc1[q], c0v, c1v);
        int h0 = 2*q, h1 = 2*q+1;
        float* o0 = outg + ((size_t)(b*HH+h0)*TT + t)*FF + f;
        float* o1 = outg + ((size_t)(b*HH+h1)*TT + t)*FF + f;
        o0[0]  = a0  + bs[h0];
        o0[FF] = c0v + bs[h0];
        o1[0]  = a1  + bs[h1];
        o1[FF] = c1v + bs[h1];
    }
}

// ============================================================
// K2: banded correlation (register-tiled band-GEMM) — unchanged
// corr[b,h,t,d] = sum_f xm1[b,h,t,f] * xf1[b,h,t+d-31,f]   (0-padded)
// ============================================================
#define K2T 64
#define K2S 70
__global__ void __launch_bounds__(256) corr_kernel()
{
    __shared__ float sm[K2T*K2S];
    __shared__ float sf[(K2T+31)*K2S];

    int b = blockIdx.z, h = blockIdx.y, t0 = blockIdx.x * K2T;
    int tid = threadIdx.x;   // 256

    const float* xmp = g_xm1 + ((size_t)(b*HH+h)*TT)*FF;
    const float* xfp = g_xf1 + ((size_t)(b*HH+h)*TT)*FF;

    for (int i = tid; i < K2T*FF; i += 256) {
        int r = i >> 6, fc = i & 63;
        sm[r*K2S + fc] = xmp[(size_t)(t0+r)*FF + fc];
    }
    for (int i = tid; i < (K2T+31)*FF; i += 256) {
        int r = i >> 6, fc = i & 63;
        int tt = t0 + r - 31;
        sf[r*K2S + fc] = (tt >= 0) ? xfp[(size_t)tt*FF + fc] : 0.f;
    }
    __syncthreads();

    int tl0 = (tid >> 3) << 1;   // 0,2,...,62
    int d0  = (tid & 7)  << 2;   // 0,4,...,28

    u64 acc[2][4];
#pragma unroll
    for (int i = 0; i < 2; i++)
#pragma unroll
        for (int j = 0; j < 4; j++) acc[i][j] = 0ull;

#pragma unroll 4
    for (int fcp = 0; fcp < FF/2; fcp++) {
        u64 a[2], br[5];
#pragma unroll
        for (int i = 0; i < 2; i++)
            a[i] = *(const u64*)(sm + (tl0+i)*K2S + fcp*2);
#pragma unroll
        for (int k = 0; k < 5; k++)
            br[k] = *(const u64*)(sf + (tl0+d0+k)*K2S + fcp*2);
#pragma unroll
        for (int i = 0; i < 2; i++)
#pragma unroll
            for (int j = 0; j < 4; j++)
                acc[i][j] = fma2(a[i], br[i+j], acc[i][j]);
    }

#pragma unroll
    for (int i = 0; i < 2; i++) {
        float4 v; float x0, x1;
        unpack2(acc[i][0], x0, x1); v.x = x0 + x1;
        unpack2(acc[i][1], x0, x1); v.y = x0 + x1;
        unpack2(acc[i][2], x0, x1); v.z = x0 + x1;
        unpack2(acc[i][3], x0, x1); v.w = x0 + x1;
        *(float4*)(g_corr + (((size_t)(b*HH+h)*TT + (t0+tl0+i))*DD + d0)) = v;
    }
}

// ============================================================
// K3: 5x3 conv over (t,d) reduced over h, + bias, mask, softmax over d
// block = (b, 8-t tile) -> grid 128. Stage 16 heads at once (2 phases).
// ============================================================
__global__ void conv_softmax_kernel(const float* __restrict__ wc,
                                    const float* __restrict__ bc)
{
    __shared__ float sc[16][12*36];
    __shared__ float wcs[HH*15];
    int tid = threadIdx.x;  // 256
    int b = blockIdx.y, t0 = blockIdx.x * 8;

    for (int i = tid; i < HH*15; i += 256) wcs[i] = wc[i];

    int d  = tid & 31;
    int tl = tid >> 5;
    float acc = 0.f;

#pragma unroll 1
    for (int ph = 0; ph < 2; ph++) {
        __syncthreads();
        const float* cpb = g_corr + ((size_t)(b*HH + ph*16)*TT)*DD;
        for (int i = tid; i < 16*12*34; i += 256) {
            int h   = i / 408;
            int rem = i - h*408;
            int r   = rem / 34;
            int col = rem - r*34;
            int tt = t0 - 3 + r, dd = col - 1;
            float v = 0.f;
            if (tt >= 0 && tt < TT && dd >= 0 && dd < DD)
                v = cpb[(size_t)h*TT*DD + (size_t)tt*DD + dd];
            sc[h][r*36 + col] = v;
        }
        __syncthreads();
#pragma unroll 1
        for (int h = 0; h < 16; h++) {
            const float* s  = sc[h] + tl*36 + d;
            const float* wv = wcs + (ph*16 + h)*15;
#pragma unroll
            for (int kh = 0; kh < 5; kh++)
#pragma unroll
                for (int kw = 0; kw < 3; kw++)
                    acc = fmaf(s[kh*36 + kw], wv[kh*3 + kw], acc);
        }
    }

    acc += bc[0];
    int t = t0 + tl;
    if (t + d < DD - 1) acc = -1e13f;

    float m = acc;
#pragma unroll
    for (int o = 16; o; o >>= 1) m = fmaxf(m, __shfl_xor_sync(0xffffffffu, m, o));
    float e = expf(acc - m);
    float s = e;
#pragma unroll
    for (int o = 16; o; o >>= 1) s += __shfl_xor_sync(0xffffffffu, s, o);

    g_w[((size_t)b*TT + t)*DD + d] = e / s;
}

// ============================================================
// K4: out[b,c,t,f] = sum_d w[b,t,d] * xf[b,c,t+d-31,f]
// 256 threads, thread = (f-quad 0..15, t-group 0..15 of 4 t).
// Weight pairs packed per (t-group, source-row): the 4 duplicated pairs
// a t-group needs at iteration rl are 32 contiguous bytes -> 2 broadcast
// LDS.128 per iter (1 wavefront each) instead of 4 scattered LDS.64.
// Zero predicates in the inner loop (weights zero-padded).
// ============================================================
#define K4T 64
__global__ void __launch_bounds__(256) out_kernel(const float* __restrict__ xf,
                                                  float* __restrict__ out)
{
    __shared__ __align__(16) float sx[(K4T+31)*FF];  // 24320 B
    __shared__ __align__(16) u64 swq[16*35*4];       // 17920 B; [tg][rl][i]

    int b = blockIdx.z, c = blockIdx.y, t0 = blockIdx.x * K4T;
    int tid = threadIdx.x;  // 256

    const float* xp = xf + ((size_t)(b*CC + c)*TT)*FF;
    for (int i = tid; i < (K4T+31)*FF; i += 256) {
        int r = i >> 6;
        int tt = t0 + r - 31;
        sx[i] = (tt >= 0) ? xp[(size_t)tt*FF + (i & 63)] : 0.f;
    }
    // swq[tg*140 + rl*4 + i] = dup pair of w[t0 + 4*tg + i, rl - i] (0 outside)
    const float* wp = g_w + ((size_t)b*TT + t0)*DD;
    for (int i = tid; i < 16*35*4; i += 256) {
        int tg  = i / 140;
        int rem = i - tg*140;
        int rl  = rem >> 2;
        int ii  = rem & 3;
        int tl  = (tg << 2) + ii;
        int dd  = rl - ii;
        float v = (dd >= 0 && dd < DD) ? wp[tl*DD + dd] : 0.f;
        swq[i] = pack2(v, v);
    }
    __syncthreads();

    int fq = tid & 15;            // f = 4*fq .. 4*fq+3
    int tg = tid >> 4;            // 0..15
    int tb = tg << 2;             // t_local base

    u64 acc[4][2];
#pragma unroll
    for (int i = 0; i < 4; i++) { acc[i][0] = 0ull; acc[i][1] = 0ull; }

    const float* xrow = sx + tb*FF + fq*4;
    const ulonglong2* wq = (const ulonglong2*)(swq + (size_t)tg*140);

#pragma unroll 5
    for (int rl = 0; rl < 35; rl++) {
        ulonglong2 xv = *(const ulonglong2*)(xrow + rl*FF);
        ulonglong2 q0 = wq[rl*2];      // pairs for i=0 (x), i=1 (y)
        ulonglong2 q1 = wq[rl*2 + 1];  // pairs for i=2 (x), i=3 (y)
        acc[0][0] = fma2(xv.x, q0.x, acc[0][0]);
        acc[0][1] = fma2(xv.y, q0.x, acc[0][1]);
        acc[1][0] = fma2(xv.x, q0.y, acc[1][0]);
        acc[1][1] = fma2(xv.y, q0.y, acc[1][1]);
        acc[2][0] = fma2(xv.x, q1.x, acc[2][0]);
        acc[2][1] = fma2(xv.y, q1.x, acc[2][1]);
        acc[3][0] = fma2(xv.x, q1.y, acc[3][0]);
        acc[3][1] = fma2(xv.y, q1.y, acc[3][1]);
    }

    float* op = out + ((size_t)(b*CC + c)*TT + (t0 + tb))*FF + fq*4;
#pragma unroll
    for (int i = 0; i < 4; i++) {
        float4 v;
        unpack2(acc[i][0], v.x, v.y);
        unpack2(acc[i][1], v.z, v.w);
        *(float4*)(op + (size_t)i*FF) = v;
    }
}

// ============================================================
extern "C" void kernel_launch(void* const* d_in, const int* in_sizes, int n_in,
                              void* d_out, int out_size)
{
    const float* xm = (const float*)d_in[0];
    const float* xf = (const float*)d_in[1];
    const float* w1 = (const float*)d_in[2];
    const float* b1 = (const float*)d_in[3];
    const float* w2 = (const float*)d_in[4];
    const float* b2 = (const float*)d_in[5];
    const float* wc = (const float*)d_in[6];
    const float* bc = (const float*)d_in[7];
    float* out = (float*)d_out;

    (void)in_sizes; (void)n_in; (void)out_size;

    proj_kernel<<<dim3(128, 2), 256>>>(xm, xf, w1, b1, w2, b2);

    dim3 g2(TT/K2T, HH, BB);
    corr_kernel<<<g2, 256>>>();

    dim3 g3(TT/8, BB);
    conv_softmax_kernel<<<g3, 256>>>(wc, bc);

    dim3 g4(TT/K4T, CC, BB);
    out_kernel<<<g4, 256>>>(xf, out);
}

// round 8
// speedup vs baseline: 1.3136x; 1.0117x over previous
#include <cuda_runtime.h>
#include <math.h>

#define BB 2
#define CC 128
#define TT 512
#define FF 64
#define HH 32
#define DD 32

typedef unsigned long long u64;

// -------- f32x2 packed-FMA helpers (sm_103a) --------
__device__ __forceinline__ u64 pack2(float lo, float hi) {
    u64 r; asm("mov.b64 %0,{%1,%2};" : "=l"(r) : "f"(lo), "f"(hi)); return r;
}
__device__ __forceinline__ void unpack2(u64 v, float& a, float& b) {
    asm("mov.b64 {%0,%1},%2;" : "=f"(a), "=f"(b) : "l"(v));
}
__device__ __forceinline__ u64 fma2(u64 a, u64 b, u64 c) {
    u64 d; asm("fma.rn.f32x2 %0,%1,%2,%3;" : "=l"(d) : "l"(a), "l"(b), "l"(c)); return d;
}

// -------- scratch (device globals: allocation-free) --------
__device__ float g_xm1[BB*HH*TT*FF];   // (b,h,t,f)
__device__ float g_xf1[BB*HH*TT*FF];   // (b,h,t,f)
__device__ float g_corr[BB*HH*TT*DD];  // (b,h,t,d)
__device__ float g_w[BB*TT*DD];        // (b,t,d) softmax weights

// ============================================================
// K1 (fused both projections): out[b,h,t,f] = sum_c x[b,c,t,f]*w[c,h] + bias[h]
// (unchanged: 256 threads, dim3(128,2))
// ============================================================
__global__ void __launch_bounds__(256) proj_kernel(
    const float* __restrict__ xm, const float* __restrict__ xf,
    const float* __restrict__ w1, const float* __restrict__ b1,
    const float* __restrict__ w2, const float* __restrict__ b2)
{
    __shared__ __align__(16) float ws[CC*HH];   // [c][h]
    __shared__ float bs[HH];
    int which = blockIdx.y;
    const float* x    = which ? xf : xm;
    const float* w    = which ? w2 : w1;
    const float* bias = which ? b2 : b1;
    float* outg = which ? g_xf1 : g_xm1;

    int tid = threadIdx.x;
    for (int i = tid; i < CC*HH; i += 256) ws[i] = w[i];
    if (tid < HH) bs[tid] = bias[tid];
    __syncthreads();

    int f  = tid & 63;
    int tp = tid >> 6;                       // 0..3
    int bx = blockIdx.x;
    int b  = bx >> 6;
    int t  = (((bx & 63) << 2) + tp) << 1;   // even t; thread does t and t+1

    u64 acc0[16], acc1[16];
#pragma unroll
    for (int i = 0; i < 16; i++) { acc0[i] = 0ull; acc1[i] = 0ull; }

    const float* xp = x + ((size_t)b*CC*TT + t)*FF + f;

#pragma unroll 1
    for (int c0 = 0; c0 < CC; c0 += 8) {
        float va[8], vb[8];
#pragma unroll
        for (int j = 0; j < 8; j++) {
            const float* p = xp + (size_t)(c0+j)*TT*FF;
            va[j] = p[0];
            vb[j] = p[FF];
        }
#pragma unroll
        for (int j = 0; j < 8; j++) {
            u64 pa = pack2(va[j], va[j]);
            u64 pb = pack2(vb[j], vb[j]);
            const ulonglong2* wq = (const ulonglong2*)(ws + (c0+j)*HH);
#pragma unroll
            for (int q = 0; q < 8; q++) {
                ulonglong2 wv = wq[q];
                acc0[2*q]   = fma2(pa, wv.x, acc0[2*q]);
                acc0[2*q+1] = fma2(pa, wv.y, acc0[2*q+1]);
                acc1[2*q]   = fma2(pb, wv.x, acc1[2*q]);
                acc1[2*q+1] = fma2(pb, wv.y, acc1[2*q+1]);
            }
        }
    }

#pragma unroll
    for (int q = 0; q < 16; q++) {
        float a0, a1, c0v, c1v;
        unpack2(acc0[q], a0, a1);
        unpack2(acc1[q], c0v, c1v);
        int h0 = 2*q, h1 = 2*q+1;
        float* o0 = outg + ((size_t)(b*HH+h0)*TT + t)*FF + f;
        float* o1 = outg + ((size_t)(b*HH+h1)*TT + t)*FF + f;
        o0[0]  = a0  + bs[h0];
        o0[FF] = c0v + bs[h0];
        o1[0]  = a1  + bs[h1];
        o1[FF] = c1v + bs[h1];
    }
}

// ============================================================
// K2: banded correlation (register-tiled band-GEMM) — unchanged
// ============================================================
#define K2T 64
#define K2S 70
__global__ void __launch_bounds__(256) corr_kernel()
{
    __shared__ float sm[K2T*K2S];
    __shared__ float sf[(K2T+31)*K2S];

    int b = blockIdx.z, h = blockIdx.y, t0 = blockIdx.x * K2T;
    int tid = threadIdx.x;   // 256

    const float* xmp = g_xm1 + ((size_t)(b*HH+h)*TT)*FF;
    const float* xfp = g_xf1 + ((size_t)(b*HH+h)*TT)*FF;

    for (int i = tid; i < K2T*FF; i += 256) {
        int r = i >> 6, fc = i & 63;
        sm[r*K2S + fc] = xmp[(size_t)(t0+r)*FF + fc];
    }
    for (int i = tid; i < (K2T+31)*FF; i += 256) {
        int r = i >> 6, fc = i & 63;
        int tt = t0 + r - 31;
        sf[r*K2S + fc] = (tt >= 0) ? xfp[(size_t)tt*FF + fc] : 0.f;
    }
    __syncthreads();

    int tl0 = (tid >> 3) << 1;   // 0,2,...,62
    int d0  = (tid & 7)  << 2;   // 0,4,...,28

    u64 acc[2][4];
#pragma unroll
    for (int i = 0; i < 2; i++)
#pragma unroll
        for (int j = 0; j < 4; j++) acc[i][j] = 0ull;

#pragma unroll 4
    for (int fcp = 0; fcp < FF/2; fcp++) {
        u64 a[2], br[5];
#pragma unroll
        for (int i = 0; i < 2; i++)
            a[i] = *(const u64*)(sm + (tl0+i)*K2S + fcp*2);
#pragma unroll
        for (int k = 0; k < 5; k++)
            br[k] = *(const u64*)(sf + (tl0+d0+k)*K2S + fcp*2);
#pragma unroll
        for (int i = 0; i < 2; i++)
#pragma unroll
            for (int j = 0; j < 4; j++)
                acc[i][j] = fma2(a[i], br[i+j], acc[i][j]);
    }

#pragma unroll
    for (int i = 0; i < 2; i++) {
        float4 v; float x0, x1;
        unpack2(acc[i][0], x0, x1); v.x = x0 + x1;
        unpack2(acc[i][1], x0, x1); v.y = x0 + x1;
        unpack2(acc[i][2], x0, x1); v.z = x0 + x1;
        unpack2(acc[i][3], x0, x1); v.w = x0 + x1;
        *(float4*)(g_corr + (((size_t)(b*HH+h)*TT + (t0+tl0+i))*DD + d0)) = v;
    }
}

// ============================================================
// K3: conv + mask + softmax — unchanged
// ============================================================
__global__ void conv_softmax_kernel(const float* __restrict__ wc,
                                    const float* __restrict__ bc)
{
    __shared__ float sc[16][12*36];
    __shared__ float wcs[HH*15];
    int tid = threadIdx.x;  // 256
    int b = blockIdx.y, t0 = blockIdx.x * 8;

    for (int i = tid; i < HH*15; i += 256) wcs[i] = wc[i];

    int d  = tid & 31;
    int tl = tid >> 5;
    float acc = 0.f;

#pragma unroll 1
    for (int ph = 0; ph < 2; ph++) {
        __syncthreads();
        const float* cpb = g_corr + ((size_t)(b*HH + ph*16)*TT)*DD;
        for (int i = tid; i < 16*12*34; i += 256) {
            int h   = i / 408;
            int rem = i - h*408;
            int r   = rem / 34;
            int col = rem - r*34;
            int tt = t0 - 3 + r, dd = col - 1;
            float v = 0.f;
            if (tt >= 0 && tt < TT && dd >= 0 && dd < DD)
                v = cpb[(size_t)h*TT*DD + (size_t)tt*DD + dd];
            sc[h][r*36 + col] = v;
        }
        __syncthreads();
#pragma unroll 1
        for (int h = 0; h < 16; h++) {
            const float* s  = sc[h] + tl*36 + d;
            const float* wv = wcs + (ph*16 + h)*15;
#pragma unroll
            for (int kh = 0; kh < 5; kh++)
#pragma unroll
                for (int kw = 0; kw < 3; kw++)
                    acc = fmaf(s[kh*36 + kw], wv[kh*3 + kw], acc);
        }
    }

    acc += bc[0];
    int t = t0 + tl;
    if (t + d < DD - 1) acc = -1e13f;

    float m = acc;
#pragma unroll
    for (int o = 16; o; o >>= 1) m = fmaxf(m, __shfl_xor_sync(0xffffffffu, m, o));
    float e = expf(acc - m);
    float s = e;
#pragma unroll
    for (int o = 16; o; o >>= 1) s += __shfl_xor_sync(0xffffffffu, s, o);

    g_w[((size_t)b*TT + t)*DD + d] = e / s;
}

// ============================================================
// K4: out[b,c,t,f] = sum_d w[b,t,d] * xf[b,c,t+d-31,f]
// R7 layout + explicit software pipelining: next iteration's 3 LDS
// issue before current iteration's 8 FFMA2 (register rotation,
// fully unrolled) -> LDS latency hidden behind fma issue.
// ============================================================
#define K4T 64
__global__ void __launch_bounds__(256) out_kernel(const float* __restrict__ xf,
                                                  float* __restrict__ out)
{
    __shared__ __align__(16) float sx[(K4T+31)*FF];  // 24320 B
    __shared__ __align__(16) u64 swq[16*35*4];       // 17920 B; [tg][rl][i]

    int b = blockIdx.z, c = blockIdx.y, t0 = blockIdx.x * K4T;
    int tid = threadIdx.x;  // 256

    const float* xp = xf + ((size_t)(b*CC + c)*TT)*FF;
    for (int i = tid; i < (K4T+31)*FF; i += 256) {
        int r = i >> 6;
        int tt = t0 + r - 31;
        sx[i] = (tt >= 0) ? xp[(size_t)tt*FF + (i & 63)] : 0.f;
    }
    // swq[tg*140 + rl*4 + i] = dup pair of w[t0 + 4*tg + i, rl - i] (0 outside)
    const float* wp = g_w + ((size_t)b*TT + t0)*DD;
    for (int i = tid; i < 16*35*4; i += 256) {
        int tg  = i / 140;
        int rem = i - tg*140;
        int rl  = rem >> 2;
        int ii  = rem & 3;
        int tl  = (tg << 2) + ii;
        int dd  = rl - ii;
        float v = (dd >= 0 && dd < DD) ? wp[tl*DD + dd] : 0.f;
        swq[i] = pack2(v, v);
    }
    __syncthreads();

    int fq = tid & 15;            // f = 4*fq .. 4*fq+3
    int tg = tid >> 4;            // 0..15
    int tb = tg << 2;             // t_local base

    u64 acc[4][2];
#pragma unroll
    for (int i = 0; i < 4; i++) { acc[i][0] = 0ull; acc[i][1] = 0ull; }

    const float* xrow = sx + tb*FF + fq*4;
    const ulonglong2* wq = (const ulonglong2*)(swq + (size_t)tg*140);

    // software pipeline: preload iter 0, rotate
    ulonglong2 xv = *(const ulonglong2*)(xrow);
    ulonglong2 q0 = wq[0];
    ulonglong2 q1 = wq[1];

#pragma unroll
    for (int rl = 0; rl < 34; rl++) {
        ulonglong2 xv_n = *(const ulonglong2*)(xrow + (rl+1)*FF);
        ulonglong2 q0_n = wq[(rl+1)*2];
        ulonglong2 q1_n = wq[(rl+1)*2 + 1];
        acc[0][0] = fma2(xv.x, q0.x, acc[0][0]);
        acc[0][1] = fma2(xv.y, q0.x, acc[0][1]);
        acc[1][0] = fma2(xv.x, q0.y, acc[1][0]);
        acc[1][1] = fma2(xv.y, q0.y, acc[1][1]);
        acc[2][0] = fma2(xv.x, q1.x, acc[2][0]);
        acc[2][1] = fma2(xv.y, q1.x, acc[2][1]);
        acc[3][0] = fma2(xv.x, q1.y, acc[3][0]);
        acc[3][1] = fma2(xv.y, q1.y, acc[3][1]);
        xv = xv_n; q0 = q0_n; q1 = q1_n;
    }
    // final iteration (rl = 34)
    acc[0][0] = fma2(xv.x, q0.x, acc[0][0]);
    acc[0][1] = fma2(xv.y, q0.x, acc[0][1]);
    acc[1][0] = fma2(xv.x, q0.y, acc[1][0]);
    acc[1][1] = fma2(xv.y, q0.y, acc[1][1]);
    acc[2][0] = fma2(xv.x, q1.x, acc[2][0]);
    acc[2][1] = fma2(xv.y, q1.x, acc[2][1]);
    acc[3][0] = fma2(xv.x, q1.y, acc[3][0]);
    acc[3][1] = fma2(xv.y, q1.y, acc[3][1]);

    float* op = out + ((size_t)(b*CC + c)*TT + (t0 + tb))*FF + fq*4;
#pragma unroll
    for (int i = 0; i < 4; i++) {
        float4 v;
        unpack2(acc[i][0], v.x, v.y);
        unpack2(acc[i][1], v.z, v.w);
        *(float4*)(op + (size_t)i*FF) = v;
    }
}

// ============================================================
extern "C" void kernel_launch(void* const* d_in, const int* in_sizes, int n_in,
                              void* d_out, int out_size)
{
    const float* xm = (const float*)d_in[0];
    const float* xf = (const float*)d_in[1];
    const float* w1 = (const float*)d_in[2];
    const float* b1 = (const float*)d_in[3];
    const float* w2 = (const float*)d_in[4];
    const float* b2 = (const float*)d_in[5];
    const float* wc = (const float*)d_in[6];
    const float* bc = (const float*)d_in[7];
    float* out = (float*)d_out;

    (void)in_sizes; (void)n_in; (void)out_size;

    proj_kernel<<<dim3(128, 2), 256>>>(xm, xf, w1, b1, w2, b2);

    dim3 g2(TT/K2T, HH, BB);
    corr_kernel<<<g2, 256>>>();

    dim3 g3(TT/8, BB);
    conv_softmax_kernel<<<g3, 256>>>(wc, bc);

    dim3 g4(TT/K4T, CC, BB);
    out_kernel<<<g4, 256>>>(xf, out);
}